// round 3
// baseline (speedup 1.0000x reference)
#include <cuda_runtime.h>
#include <cuda_bf16.h>
#include <math.h>

#define NN 50000
#define NE 800000
#define NG 256
#define HID 128
#define BN_EPS 1e-5f

// ---------------- persistent scratch (device globals; no allocations) ----------------
__device__ int   g_deg[NN];
__device__ int   g_fill[NN];
__device__ int   g_rowptr[NN + 1];
__device__ int   g_src[NE];
__device__ float g_invdeg[NN];
__device__ float g_agg[(long)NN * HID];   // aggregated neighbor features (layer0 uses stride 64)
__device__ float g_hpre[(long)NN * HID];  // pre-BN activations
__device__ float g_h[(long)NN * HID];     // post-BN activations (layer input)
__device__ float g_colsum[HID];
__device__ float g_colsumsq[HID];
__device__ float g_pooled[NG * HID];
__device__ float g_gcount[NG];

__device__ __forceinline__ int clampi(int v, int hi) {  // clamp to [0, hi]
    return min(max(v, 0), hi);
}

// ---------------- setup kernels ----------------
__global__ void k_zero_main() {
    int i = blockIdx.x * blockDim.x + threadIdx.x;
    if (i < NN) { g_deg[i] = 0; g_fill[i] = 0; }
    if (i < NG * HID) g_pooled[i] = 0.0f;
    if (i < NG) g_gcount[i] = 0.0f;
}

// edge_index is int32 on device: ei[0..NE) = src, ei[NE..2NE) = dst
__global__ void k_deg_batch(const int* __restrict__ ei,
                            const int* __restrict__ batch) {
    int i = blockIdx.x * blockDim.x + threadIdx.x;
    if (i < NE) atomicAdd(&g_deg[clampi(ei[NE + i], NN - 1)], 1);
    if (i < NN) atomicAdd(&g_gcount[clampi(batch[i], NG - 1)], 1.0f);
}

// single-block exclusive scan of degrees -> rowptr, plus inv_deg
__global__ void k_scan() {
    __shared__ int ssum[1024];
    int t = threadIdx.x;
    const int C = (NN + 1023) / 1024;   // 49
    int begin = t * C;
    int end   = min(begin + C, NN);
    int s = 0;
    for (int i = begin; i < end; i++) s += g_deg[i];
    ssum[t] = s;
    __syncthreads();
    for (int off = 1; off < 1024; off <<= 1) {
        int v = (t >= off) ? ssum[t - off] : 0;
        __syncthreads();
        ssum[t] += v;
        __syncthreads();
    }
    int run = (t > 0) ? ssum[t - 1] : 0;
    for (int i = begin; i < end; i++) {
        g_rowptr[i] = run;
        int d = g_deg[i];
        run += d;
        g_invdeg[i] = 1.0f / fmaxf((float)d, 1.0f);
    }
    if (t == 1023) g_rowptr[NN] = ssum[1023];
}

__global__ void k_fill(const int* __restrict__ ei) {
    int i = blockIdx.x * blockDim.x + threadIdx.x;
    if (i >= NE) return;
    int d = clampi(ei[NE + i], NN - 1);
    int p = atomicAdd(&g_fill[d], 1);
    int slot = g_rowptr[d] + p;
    if (slot < NE) g_src[slot] = clampi(ei[i], NN - 1);
}

// ---- aggregation into g_agg: agg[n][f] = inv_deg[n] * sum_{e in CSR(n)} in[src[e]][f] ----
template <int F, bool FROMH>
__global__ void k_aggregate(const float* __restrict__ xin) {
    const float* __restrict__ in = FROMH ? (const float*)g_h : xin;
    const int nodesPerBlock = 256 / F;
    int node = blockIdx.x * nodesPerBlock + threadIdx.x / F;
    int f = threadIdx.x % F;
    if (node >= NN) return;
    int s = g_rowptr[node], e = g_rowptr[node + 1];
    float acc = 0.0f;
    int i = s;
    for (; i + 1 < e; i += 2) {
        int s0 = g_src[i];
        int s1 = g_src[i + 1];
        acc += in[(long)s0 * F + f];
        acc += in[(long)s1 * F + f];
    }
    if (i < e) acc += in[(long)g_src[i] * F + f];
    g_agg[(long)node * F + f] = acc * g_invdeg[node];
}

__global__ void k_zero_sums() {
    int i = threadIdx.x;
    if (i < HID) { g_colsum[i] = 0.0f; g_colsumsq[i] = 0.0f; }
}

// ---- fused dual GEMM: g_hpre = g_agg@W1 + A2@W2 + bias, [NN,128] ----
// BM=128 BN=128 BK=8, 256 threads, 8x8 per thread.
template <int K, bool A2H>
__global__ void k_gemm(const float* __restrict__ A2x,
                       const float* __restrict__ W1, const float* __restrict__ W2,
                       const float* __restrict__ bias) {
    __shared__ float As[8][128];
    __shared__ float Bs[8][128];
    int tid = threadIdx.x;
    int blockRow = blockIdx.x * 128;
    int ty = tid / 16, tx = tid % 16;
    float acc[8][8];
#pragma unroll
    for (int i = 0; i < 8; i++)
#pragma unroll
        for (int j = 0; j < 8; j++) acc[i][j] = 0.0f;

    const float* Aseg = (const float*)g_agg;
    const float* Wseg = W1;
    for (int seg = 0; seg < 2; seg++) {
        for (int k0 = 0; k0 < K; k0 += 8) {
            {
                int r  = tid >> 1;
                int kk = (tid & 1) * 4;
                int gr = blockRow + r;
                float4 v = make_float4(0.f, 0.f, 0.f, 0.f);
                if (gr < NN) v = *(const float4*)(Aseg + (long)gr * K + k0 + kk);
                As[kk + 0][r] = v.x;
                As[kk + 1][r] = v.y;
                As[kk + 2][r] = v.z;
                As[kk + 3][r] = v.w;
            }
            {
                int kk = tid >> 5;
                int nn = (tid & 31) * 4;
                float4 v = *(const float4*)(Wseg + (long)(k0 + kk) * 128 + nn);
                *(float4*)&Bs[kk][nn] = v;
            }
            __syncthreads();
#pragma unroll
            for (int k = 0; k < 8; k++) {
                float a[8], b[8];
#pragma unroll
                for (int i = 0; i < 8; i++) a[i] = As[k][ty * 8 + i];
#pragma unroll
                for (int j = 0; j < 8; j++) b[j] = Bs[k][tx * 8 + j];
#pragma unroll
                for (int i = 0; i < 8; i++)
#pragma unroll
                    for (int j = 0; j < 8; j++) acc[i][j] += a[i] * b[j];
            }
            __syncthreads();
        }
        Aseg = A2H ? (const float*)g_h : A2x;
        Wseg = W2;
    }
#pragma unroll
    for (int i = 0; i < 8; i++) {
        int gr = blockRow + ty * 8 + i;
        if (gr < NN) {
#pragma unroll
            for (int j = 0; j < 8; j += 4) {
                int col = tx * 8 + j;
                float4 v;
                v.x = acc[i][j + 0] + bias[col + 0];
                v.y = acc[i][j + 1] + bias[col + 1];
                v.z = acc[i][j + 2] + bias[col + 2];
                v.w = acc[i][j + 3] + bias[col + 3];
                *(float4*)(g_hpre + (long)gr * 128 + col) = v;
            }
        }
    }
}

// ---------------- BN stats: per-column sum & sumsq over g_hpre ----------------
__global__ void k_bn_stats() {
    const int ROWS_PER_BLOCK = 200;
    int col = threadIdx.x;                 // 128 threads
    int r0 = blockIdx.x * ROWS_PER_BLOCK;
    int r1 = min(r0 + ROWS_PER_BLOCK, NN);
    float s = 0.0f, s2 = 0.0f;
    for (int r = r0; r < r1; r++) {
        float v = g_hpre[(long)r * 128 + col];
        s += v;
        s2 += v * v;
    }
    atomicAdd(&g_colsum[col], s);
    atomicAdd(&g_colsumsq[col], s2);
}

// ---------- BN apply + ReLU: g_h = relu(bn(g_hpre)); optional fused pooling ----------
__global__ void k_bn_apply(const float* __restrict__ gamma, const float* __restrict__ beta,
                           const int* __restrict__ batch, int do_pool) {
    long i = (long)blockIdx.x * blockDim.x + threadIdx.x;
    if (i >= (long)NN * 128) return;
    int col = (int)(i & 127);
    int row = (int)(i >> 7);
    const float invN = 1.0f / (float)NN;
    float mu = g_colsum[col] * invN;
    float var = g_colsumsq[col] * invN - mu * mu;
    float v = (g_hpre[i] - mu) * rsqrtf(var + BN_EPS) * gamma[col] + beta[col];
    v = fmaxf(v, 0.0f);
    g_h[i] = v;
    if (do_pool) atomicAdd(&g_pooled[clampi(batch[row], NG - 1) * 128 + col], v);
}

// ---------------- final MLP + sigmoid ----------------
__global__ void k_mlp(const float* __restrict__ fc1W, const float* __restrict__ fc1b,
                      const float* __restrict__ fc2W, const float* __restrict__ fc2b,
                      float* __restrict__ out) {
    int g = blockIdx.x;          // 256 blocks
    int t = threadIdx.x;         // 64 threads
    __shared__ float p[128];
    __shared__ float zred[2];
    float cnt = fmaxf(g_gcount[g], 1.0f);
    p[t]      = g_pooled[g * 128 + t] / cnt;
    p[t + 64] = g_pooled[g * 128 + 64 + t] / cnt;
    __syncthreads();
    float z = fc1b[t];
#pragma unroll 8
    for (int k = 0; k < 128; k++) z += p[k] * fc1W[k * 64 + t];
    z = fmaxf(z, 0.0f) * fc2W[t];
#pragma unroll
    for (int off = 16; off; off >>= 1) z += __shfl_down_sync(0xffffffffu, z, off);
    if ((t & 31) == 0) zred[t >> 5] = z;
    __syncthreads();
    if (t == 0) {
        float s = zred[0] + zred[1] + fc2b[0];
        out[g] = 1.0f / (1.0f + expf(-s));
    }
}

// ---------------- host launcher: kernel launches ONLY ----------------
extern "C" void kernel_launch(void* const* d_in, const int* in_sizes, int n_in,
                              void* d_out, int out_size) {
    const float* x     = (const float*)d_in[0];
    const int*   ei    = (const int*)d_in[1];     // int64 narrowed to int32 by harness
    const int*   batch = (const int*)d_in[2];     // int64 narrowed to int32 by harness
    const float* Wn0 = (const float*)d_in[3];
    const float* Wr0 = (const float*)d_in[4];
    const float* b0  = (const float*)d_in[5];
    const float* Wn1 = (const float*)d_in[6];
    const float* Wr1 = (const float*)d_in[7];
    const float* b1  = (const float*)d_in[8];
    const float* Wn2 = (const float*)d_in[9];
    const float* Wr2 = (const float*)d_in[10];
    const float* b2  = (const float*)d_in[11];
    const float* gamma = (const float*)d_in[12]; // [3,128]
    const float* beta  = (const float*)d_in[13];
    const float* fc1W = (const float*)d_in[14];
    const float* fc1b = (const float*)d_in[15];
    const float* fc2W = (const float*)d_in[16];
    const float* fc2b = (const float*)d_in[17];
    float* out = (float*)d_out;

    // ---- graph structure (rebuilt every call; deterministic) ----
    k_zero_main<<<(NN + 255) / 256, 256>>>();
    k_deg_batch<<<(NE + 255) / 256, 256>>>(ei, batch);
    k_scan<<<1, 1024>>>();
    k_fill<<<(NE + 255) / 256, 256>>>(ei);

    const int gemmGrid = (NN + 127) / 128;
    const int bnApplyGrid = (int)(((long)NN * 128 + 255) / 256);
    const int statsGrid = (NN + 199) / 200;

    // ---- layer 0: in_dim 64 ----
    k_aggregate<64, false><<<(NN + 3) / 4, 256>>>(x);
    k_zero_sums<<<1, 256>>>();
    k_gemm<64, false><<<gemmGrid, 256>>>(x, Wn0, Wr0, b0);
    k_bn_stats<<<statsGrid, 128>>>();
    k_bn_apply<<<bnApplyGrid, 256>>>(gamma + 0 * HID, beta + 0 * HID, batch, 0);

    // ---- layer 1 ----
    k_aggregate<128, true><<<(NN + 1) / 2, 256>>>(nullptr);
    k_zero_sums<<<1, 256>>>();
    k_gemm<128, true><<<gemmGrid, 256>>>(nullptr, Wn1, Wr1, b1);
    k_bn_stats<<<statsGrid, 128>>>();
    k_bn_apply<<<bnApplyGrid, 256>>>(gamma + 1 * HID, beta + 1 * HID, batch, 0);

    // ---- layer 2 (pooling fused into BN apply) ----
    k_aggregate<128, true><<<(NN + 1) / 2, 256>>>(nullptr);
    k_zero_sums<<<1, 256>>>();
    k_gemm<128, true><<<gemmGrid, 256>>>(nullptr, Wn2, Wr2, b2);
    k_bn_stats<<<statsGrid, 128>>>();
    k_bn_apply<<<bnApplyGrid, 256>>>(gamma + 2 * HID, beta + 2 * HID, batch, 1);

    // ---- MLP head ----
    k_mlp<<<NG, 64>>>(fc1W, fc1b, fc2W, fc2b, out);
}

// round 4
// speedup vs baseline: 1.4749x; 1.4749x over previous
#include <cuda_runtime.h>
#include <cuda_bf16.h>
#include <math.h>

#define NN 50000
#define NE 800000
#define NG 256
#define HID 128
#define BN_EPS 1e-5f

// ---------------- persistent scratch (device globals; no allocations) ----------------
__device__ int   g_deg[NN];
__device__ int   g_fill[NN];
__device__ int   g_rowptr[NN + 1];
__device__ int   g_src[NE];
__device__ float g_invdeg[NN];
__device__ float g_agg[(long)NN * HID];   // aggregated neighbor features (layer0 uses stride 64)
__device__ float g_hpre[(long)NN * HID];  // pre-BN activations
__device__ float g_h[(long)NN * HID];     // post-BN activations (layer input)
__device__ float g_colsum[3][HID];
__device__ float g_colsumsq[3][HID];
__device__ float g_pooled[NG * HID];
__device__ float g_gcount[NG];

__device__ __forceinline__ int clampi(int v, int hi) { return min(max(v, 0), hi); }

__device__ __forceinline__ float cvt_tf32(float x) {
    unsigned u;
    asm("cvt.rna.tf32.f32 %0, %1;" : "=r"(u) : "f"(x));
    return __uint_as_float(u);
}

__device__ __forceinline__ void mma_tf32(float c[4], const float a[4], const float b[2]) {
    asm volatile(
        "mma.sync.aligned.m16n8k8.row.col.f32.tf32.tf32.f32 "
        "{%0,%1,%2,%3}, {%4,%5,%6,%7}, {%8,%9}, {%0,%1,%2,%3};"
        : "+f"(c[0]), "+f"(c[1]), "+f"(c[2]), "+f"(c[3])
        : "r"(__float_as_uint(a[0])), "r"(__float_as_uint(a[1])),
          "r"(__float_as_uint(a[2])), "r"(__float_as_uint(a[3])),
          "r"(__float_as_uint(b[0])), "r"(__float_as_uint(b[1])));
}

// ---------------- setup kernels ----------------
__global__ void k_zero_main() {
    int i = blockIdx.x * blockDim.x + threadIdx.x;
    if (i < NN) { g_deg[i] = 0; g_fill[i] = 0; }
    if (i < NG * HID) g_pooled[i] = 0.0f;
    if (i < NG) g_gcount[i] = 0.0f;
    if (i < 3 * HID) { ((float*)g_colsum)[i] = 0.0f; ((float*)g_colsumsq)[i] = 0.0f; }
}

// edge_index is int32 on device: ei[0..NE) = src, ei[NE..2NE) = dst
__global__ void k_deg_batch(const int* __restrict__ ei, const int* __restrict__ batch) {
    int i = blockIdx.x * blockDim.x + threadIdx.x;
    if (i < NE) atomicAdd(&g_deg[clampi(ei[NE + i], NN - 1)], 1);
    if (i < NN) atomicAdd(&g_gcount[clampi(batch[i], NG - 1)], 1.0f);
}

// single-block exclusive scan of degrees -> rowptr, plus inv_deg
__global__ void k_scan() {
    __shared__ int ssum[1024];
    int t = threadIdx.x;
    const int C = (NN + 1023) / 1024;
    int begin = t * C;
    int end   = min(begin + C, NN);
    int s = 0;
    for (int i = begin; i < end; i++) s += g_deg[i];
    ssum[t] = s;
    __syncthreads();
    for (int off = 1; off < 1024; off <<= 1) {
        int v = (t >= off) ? ssum[t - off] : 0;
        __syncthreads();
        ssum[t] += v;
        __syncthreads();
    }
    int run = (t > 0) ? ssum[t - 1] : 0;
    for (int i = begin; i < end; i++) {
        g_rowptr[i] = run;
        int d = g_deg[i];
        run += d;
        g_invdeg[i] = 1.0f / fmaxf((float)d, 1.0f);
    }
    if (t == 1023) g_rowptr[NN] = ssum[1023];
}

__global__ void k_fill(const int* __restrict__ ei) {
    int i = blockIdx.x * blockDim.x + threadIdx.x;
    if (i >= NE) return;
    int d = clampi(ei[NE + i], NN - 1);
    int p = atomicAdd(&g_fill[d], 1);
    int slot = g_rowptr[d] + p;
    if (slot < NE) g_src[slot] = clampi(ei[i], NN - 1);
}

// ---- aggregation (float4): agg[n][:] = inv_deg[n] * sum_{e in CSR(n)} in[src[e]][:] ----
template <int F, bool FROMH>
__global__ void k_aggregate(const float* __restrict__ xin) {
    const float4* __restrict__ in = (const float4*)(FROMH ? (const float*)g_h : xin);
    const int TPN = F / 4;                       // 32 (F=128) or 16 (F=64)
    int node = blockIdx.x * (256 / TPN) + threadIdx.x / TPN;
    int f = threadIdx.x % TPN;
    if (node >= NN) return;
    int s = g_rowptr[node], e = g_rowptr[node + 1];
    float4 acc = make_float4(0.f, 0.f, 0.f, 0.f);
    int i = s;
    for (; i + 1 < e; i += 2) {
        float4 v0 = in[(size_t)g_src[i] * TPN + f];
        float4 v1 = in[(size_t)g_src[i + 1] * TPN + f];
        acc.x += v0.x + v1.x; acc.y += v0.y + v1.y;
        acc.z += v0.z + v1.z; acc.w += v0.w + v1.w;
    }
    if (i < e) {
        float4 v = in[(size_t)g_src[i] * TPN + f];
        acc.x += v.x; acc.y += v.y; acc.z += v.z; acc.w += v.w;
    }
    float id = g_invdeg[node];
    ((float4*)g_agg)[(size_t)node * TPN + f] =
        make_float4(acc.x * id, acc.y * id, acc.z * id, acc.w * id);
}

// ---- TF32 dual GEMM: g_hpre = g_agg@W1 + A2@W2 + bias, [NN,128] ----
// BM=128, BN=128, BK=16; 256 threads = 8 warps (2M x 4N), warp tile 64x32.
template <int K, bool A2H>
__global__ void __launch_bounds__(256, 2)
k_gemm_tf32(const float* __restrict__ A2x,
            const float* __restrict__ W1, const float* __restrict__ W2,
            const float* __restrict__ bias) {
    __shared__ float As[128 * 17];     // [row][k], stride 17
    __shared__ float Bs[16 * 136];     // [k][n],  stride 136
    __shared__ float bsh[128];

    int tid = threadIdx.x;
    int lane = tid & 31;
    int wid = tid >> 5;
    int warp_m = wid & 1;              // 64 rows each
    int warp_n = wid >> 1;             // 32 cols each
    int g = lane >> 2;                 // 0..7
    int tg = lane & 3;                 // 0..3
    int blockRow = blockIdx.x * 128;

    if (tid < 128) bsh[tid] = bias[tid];

    float acc[4][4][4];
#pragma unroll
    for (int mt = 0; mt < 4; mt++)
#pragma unroll
        for (int nt = 0; nt < 4; nt++)
#pragma unroll
            for (int q = 0; q < 4; q++) acc[mt][nt][q] = 0.0f;

    const float* Aseg = (const float*)g_agg;
    const float* Wseg = W1;
#pragma unroll 1
    for (int seg = 0; seg < 2; seg++) {
#pragma unroll 1
        for (int k0 = 0; k0 < K; k0 += 16) {
            // A tile: 128 rows x 16 k (tf32-rounded)
#pragma unroll
            for (int j = 0; j < 2; j++) {
                int idx = tid + 256 * j;           // 0..511
                int r = idx >> 2;
                int kk = (idx & 3) * 4;
                int gr = blockRow + r;
                float4 v = make_float4(0.f, 0.f, 0.f, 0.f);
                if (gr < NN) v = *(const float4*)(Aseg + (size_t)gr * K + k0 + kk);
                As[r * 17 + kk + 0] = cvt_tf32(v.x);
                As[r * 17 + kk + 1] = cvt_tf32(v.y);
                As[r * 17 + kk + 2] = cvt_tf32(v.z);
                As[r * 17 + kk + 3] = cvt_tf32(v.w);
            }
            // B tile: 16 k x 128 n (tf32-rounded)
#pragma unroll
            for (int j = 0; j < 2; j++) {
                int idx = tid + 256 * j;
                int kk = idx >> 5;                 // 0..15
                int nn = (idx & 31) * 4;
                float4 v = *(const float4*)(Wseg + (size_t)(k0 + kk) * 128 + nn);
                float4 t = make_float4(cvt_tf32(v.x), cvt_tf32(v.y),
                                       cvt_tf32(v.z), cvt_tf32(v.w));
                *(float4*)&Bs[kk * 136 + nn] = t;
            }
            __syncthreads();
#pragma unroll
            for (int k8 = 0; k8 < 16; k8 += 8) {
                float a[4][4], b[4][2];
#pragma unroll
                for (int mt = 0; mt < 4; mt++) {
                    int r = warp_m * 64 + mt * 16 + g;
                    a[mt][0] = As[r * 17 + k8 + tg];
                    a[mt][1] = As[(r + 8) * 17 + k8 + tg];
                    a[mt][2] = As[r * 17 + k8 + tg + 4];
                    a[mt][3] = As[(r + 8) * 17 + k8 + tg + 4];
                }
#pragma unroll
                for (int nt = 0; nt < 4; nt++) {
                    int c = warp_n * 32 + nt * 8 + g;
                    b[nt][0] = Bs[(k8 + tg) * 136 + c];
                    b[nt][1] = Bs[(k8 + tg + 4) * 136 + c];
                }
#pragma unroll
                for (int mt = 0; mt < 4; mt++)
#pragma unroll
                    for (int nt = 0; nt < 4; nt++)
                        mma_tf32(acc[mt][nt], a[mt], b[nt]);
            }
            __syncthreads();
        }
        Aseg = A2H ? (const float*)g_h : A2x;
        Wseg = W2;
    }
    // epilogue: C += bias -> g_hpre
#pragma unroll
    for (int mt = 0; mt < 4; mt++) {
        int r0 = blockRow + warp_m * 64 + mt * 16 + g;
#pragma unroll
        for (int nt = 0; nt < 4; nt++) {
            int c = warp_n * 32 + nt * 8 + 2 * tg;
            if (r0 < NN) {
                float2 v = make_float2(acc[mt][nt][0] + bsh[c], acc[mt][nt][1] + bsh[c + 1]);
                *(float2*)(g_hpre + (size_t)r0 * 128 + c) = v;
            }
            if (r0 + 8 < NN) {
                float2 v = make_float2(acc[mt][nt][2] + bsh[c], acc[mt][nt][3] + bsh[c + 1]);
                *(float2*)(g_hpre + (size_t)(r0 + 8) * 128 + c) = v;
            }
        }
    }
}

// ---------------- BN stats: per-column sum & sumsq over g_hpre ----------------
__global__ void k_bn_stats(int layer) {
    const int ROWS_PER_BLOCK = 200;
    int col = threadIdx.x;                 // 128 threads
    int r0 = blockIdx.x * ROWS_PER_BLOCK;
    int r1 = min(r0 + ROWS_PER_BLOCK, NN);
    float s = 0.0f, s2 = 0.0f;
    for (int r = r0; r < r1; r++) {
        float v = g_hpre[(size_t)r * 128 + col];
        s += v;
        s2 += v * v;
    }
    atomicAdd(&g_colsum[layer][col], s);
    atomicAdd(&g_colsumsq[layer][col], s2);
}

// ---------- BN apply + ReLU (float4): g_h = relu(bn(g_hpre)); optional fused pooling ----------
__global__ void k_bn_apply(const float* __restrict__ gamma, const float* __restrict__ beta,
                           const int* __restrict__ batch, int layer, int do_pool) {
    int i = blockIdx.x * blockDim.x + threadIdx.x;   // over NN*32 float4s
    if (i >= NN * 32) return;
    int row = i >> 5;
    int c0 = (i & 31) * 4;
    const float invN = 1.0f / (float)NN;
    float4 hv = ((const float4*)g_hpre)[i];
    float o[4] = {hv.x, hv.y, hv.z, hv.w};
#pragma unroll
    for (int j = 0; j < 4; j++) {
        int col = c0 + j;
        float mu = g_colsum[layer][col] * invN;
        float var = g_colsumsq[layer][col] * invN - mu * mu;
        float v = (o[j] - mu) * rsqrtf(var + BN_EPS) * gamma[col] + beta[col];
        o[j] = fmaxf(v, 0.0f);
    }
    ((float4*)g_h)[i] = make_float4(o[0], o[1], o[2], o[3]);
    if (do_pool) {
        int b = clampi(batch[row], NG - 1);
        float* p = &g_pooled[b * 128 + c0];
        atomicAdd(p + 0, o[0]);
        atomicAdd(p + 1, o[1]);
        atomicAdd(p + 2, o[2]);
        atomicAdd(p + 3, o[3]);
    }
}

// ---------------- final MLP + sigmoid ----------------
__global__ void k_mlp(const float* __restrict__ fc1W, const float* __restrict__ fc1b,
                      const float* __restrict__ fc2W, const float* __restrict__ fc2b,
                      float* __restrict__ out) {
    int g = blockIdx.x;          // 256 blocks
    int t = threadIdx.x;         // 64 threads
    __shared__ float p[128];
    __shared__ float zred[2];
    float cnt = fmaxf(g_gcount[g], 1.0f);
    p[t]      = g_pooled[g * 128 + t] / cnt;
    p[t + 64] = g_pooled[g * 128 + 64 + t] / cnt;
    __syncthreads();
    float z = fc1b[t];
#pragma unroll 8
    for (int k = 0; k < 128; k++) z += p[k] * fc1W[k * 64 + t];
    z = fmaxf(z, 0.0f) * fc2W[t];
#pragma unroll
    for (int off = 16; off; off >>= 1) z += __shfl_down_sync(0xffffffffu, z, off);
    if ((t & 31) == 0) zred[t >> 5] = z;
    __syncthreads();
    if (t == 0) {
        float s = zred[0] + zred[1] + fc2b[0];
        out[g] = 1.0f / (1.0f + expf(-s));
    }
}

// ---------------- host launcher: kernel launches ONLY ----------------
extern "C" void kernel_launch(void* const* d_in, const int* in_sizes, int n_in,
                              void* d_out, int out_size) {
    const float* x     = (const float*)d_in[0];
    const int*   ei    = (const int*)d_in[1];     // int64 narrowed to int32 by harness
    const int*   batch = (const int*)d_in[2];
    const float* Wn0 = (const float*)d_in[3];
    const float* Wr0 = (const float*)d_in[4];
    const float* b0  = (const float*)d_in[5];
    const float* Wn1 = (const float*)d_in[6];
    const float* Wr1 = (const float*)d_in[7];
    const float* b1  = (const float*)d_in[8];
    const float* Wn2 = (const float*)d_in[9];
    const float* Wr2 = (const float*)d_in[10];
    const float* b2  = (const float*)d_in[11];
    const float* gamma = (const float*)d_in[12]; // [3,128]
    const float* beta  = (const float*)d_in[13];
    const float* fc1W = (const float*)d_in[14];
    const float* fc1b = (const float*)d_in[15];
    const float* fc2W = (const float*)d_in[16];
    const float* fc2b = (const float*)d_in[17];
    float* out = (float*)d_out;

    // ---- graph structure (rebuilt every call; deterministic) ----
    k_zero_main<<<(NN + 255) / 256, 256>>>();
    k_deg_batch<<<(NE + 255) / 256, 256>>>(ei, batch);
    k_scan<<<1, 1024>>>();
    k_fill<<<(NE + 255) / 256, 256>>>(ei);

    const int gemmGrid = (NN + 127) / 128;
    const int bnApplyGrid = (NN * 32 + 255) / 256;
    const int statsGrid = (NN + 199) / 200;

    // ---- layer 0: in_dim 64 ----
    k_aggregate<64, false><<<(NN + 15) / 16, 256>>>(x);
    k_gemm_tf32<64, false><<<gemmGrid, 256>>>(x, Wn0, Wr0, b0);
    k_bn_stats<<<statsGrid, 128>>>(0);
    k_bn_apply<<<bnApplyGrid, 256>>>(gamma + 0 * HID, beta + 0 * HID, batch, 0, 0);

    // ---- layer 1 ----
    k_aggregate<128, true><<<(NN + 7) / 8, 256>>>(nullptr);
    k_gemm_tf32<128, true><<<gemmGrid, 256>>>(nullptr, Wn1, Wr1, b1);
    k_bn_stats<<<statsGrid, 128>>>(1);
    k_bn_apply<<<bnApplyGrid, 256>>>(gamma + 1 * HID, beta + 1 * HID, batch, 1, 0);

    // ---- layer 2 (pooling fused into BN apply) ----
    k_aggregate<128, true><<<(NN + 7) / 8, 256>>>(nullptr);
    k_gemm_tf32<128, true><<<gemmGrid, 256>>>(nullptr, Wn2, Wr2, b2);
    k_bn_stats<<<statsGrid, 128>>>(2);
    k_bn_apply<<<bnApplyGrid, 256>>>(gamma + 2 * HID, beta + 2 * HID, batch, 2, 1);

    // ---- MLP head ----
    k_mlp<<<NG, 64>>>(fc1W, fc1b, fc2W, fc2b, out);
}

// round 6
// speedup vs baseline: 1.5618x; 1.0589x over previous
#include <cuda_runtime.h>
#include <cuda_bf16.h>
#include <math.h>

#define NN 50000
#define NE 800000
#define NG 256
#define HID 128
#define BN_EPS 1e-5f

// ---------------- persistent scratch (device globals; no allocations) ----------------
__device__ int   g_deg[NN];
__device__ int   g_fill[NN];
__device__ int   g_rowptr[NN + 1];
__device__ int   g_src[NE];
__device__ float g_invdeg[NN];
__device__ __nv_bfloat16 g_xb[(size_t)NN * 64];     // x converted to bf16
__device__ __nv_bfloat16 g_aggb[(size_t)NN * HID];  // aggregated neighbors, bf16
__device__ __nv_bfloat16 g_hb[(size_t)NN * HID];    // post-BN activations, bf16
__device__ float g_hpre[(size_t)NN * HID];          // GEMM output (pre-BN), fp32
__device__ float g_colsum[3][HID];                  // raw acc column sums
__device__ float g_colsumsq[3][HID];
__device__ float g_pooled[NG * HID];
__device__ float g_gcount[NG];

__device__ __forceinline__ int clampi(int v, int hi) { return min(max(v, 0), hi); }

__device__ __forceinline__ void mma_bf16(float c[4], const unsigned a[4], const unsigned b[2]) {
    asm volatile(
        "mma.sync.aligned.m16n8k16.row.col.f32.bf16.bf16.f32 "
        "{%0,%1,%2,%3}, {%4,%5,%6,%7}, {%8,%9}, {%0,%1,%2,%3};"
        : "+f"(c[0]), "+f"(c[1]), "+f"(c[2]), "+f"(c[3])
        : "r"(a[0]), "r"(a[1]), "r"(a[2]), "r"(a[3]), "r"(b[0]), "r"(b[1]));
}

// ---------------- setup kernels ----------------
__global__ void k_zero_main() {
    int i = blockIdx.x * blockDim.x + threadIdx.x;
    if (i < NN) { g_deg[i] = 0; g_fill[i] = 0; }
    if (i < NG * HID) g_pooled[i] = 0.0f;
    if (i < NG) g_gcount[i] = 0.0f;
    if (i < 3 * HID) { ((float*)g_colsum)[i] = 0.0f; ((float*)g_colsumsq)[i] = 0.0f; }
}

// edge_index is int32 on device: ei[0..NE) = src, ei[NE..2NE) = dst
__global__ void k_deg_batch(const int* __restrict__ ei, const int* __restrict__ batch) {
    int i = blockIdx.x * blockDim.x + threadIdx.x;
    if (i < NE) atomicAdd(&g_deg[clampi(ei[NE + i], NN - 1)], 1);
    if (i < NN) atomicAdd(&g_gcount[clampi(batch[i], NG - 1)], 1.0f);
}

// single-block exclusive scan of degrees -> rowptr, plus inv_deg
__global__ void k_scan() {
    __shared__ int ssum[1024];
    int t = threadIdx.x;
    const int C = (NN + 1023) / 1024;
    int begin = t * C;
    int end   = min(begin + C, NN);
    int s = 0;
    for (int i = begin; i < end; i++) s += g_deg[i];
    ssum[t] = s;
    __syncthreads();
    for (int off = 1; off < 1024; off <<= 1) {
        int v = (t >= off) ? ssum[t - off] : 0;
        __syncthreads();
        ssum[t] += v;
        __syncthreads();
    }
    int run = (t > 0) ? ssum[t - 1] : 0;
    for (int i = begin; i < end; i++) {
        g_rowptr[i] = run;
        int d = g_deg[i];
        run += d;
        g_invdeg[i] = 1.0f / fmaxf((float)d, 1.0f);
    }
    if (t == 1023) g_rowptr[NN] = ssum[1023];
}

__global__ void k_fill(const int* __restrict__ ei) {
    int i = blockIdx.x * blockDim.x + threadIdx.x;
    if (i >= NE) return;
    int d = clampi(ei[NE + i], NN - 1);
    int p = atomicAdd(&g_fill[d], 1);
    int slot = g_rowptr[d] + p;
    if (slot < NE) g_src[slot] = clampi(ei[i], NN - 1);
}

// ---------------- x -> bf16 ----------------
__global__ void k_cvt_x(const float* __restrict__ x) {
    int i = blockIdx.x * blockDim.x + threadIdx.x;   // NN*16 float4s
    if (i >= NN * 16) return;
    float4 v = ((const float4*)x)[i];
    __nv_bfloat162 lo = __float22bfloat162_rn(make_float2(v.x, v.y));
    __nv_bfloat162 hi = __float22bfloat162_rn(make_float2(v.z, v.w));
    uint2 o;
    o.x = *(unsigned*)&lo;
    o.y = *(unsigned*)&hi;
    ((uint2*)g_xb)[i] = o;
}

// ---- aggregation (bf16 in, bf16 out): agg[n][:] = inv_deg[n] * sum in[src][:] ----
template <int F, bool FROMX>
__global__ void k_aggregate() {
    const uint4* __restrict__ in = (const uint4*)(FROMX ? g_xb : g_hb);
    const int TPN = F / 8;                       // uint4 = 8 bf16
    int node = blockIdx.x * (256 / TPN) + threadIdx.x / TPN;
    int f = threadIdx.x % TPN;
    if (node >= NN) return;
    int s = g_rowptr[node], e = g_rowptr[node + 1];
    float2 acc[4];
#pragma unroll
    for (int j = 0; j < 4; j++) acc[j] = make_float2(0.f, 0.f);
    for (int i = s; i < e; i++) {
        uint4 v = in[(size_t)g_src[i] * TPN + f];
        unsigned w[4] = {v.x, v.y, v.z, v.w};
#pragma unroll
        for (int j = 0; j < 4; j++) {
            float2 p = __bfloat1622float2(*(__nv_bfloat162*)&w[j]);
            acc[j].x += p.x;
            acc[j].y += p.y;
        }
    }
    float id = g_invdeg[node];
    uint4 o;
    unsigned* ow = (unsigned*)&o;
#pragma unroll
    for (int j = 0; j < 4; j++) {
        __nv_bfloat162 b = __float22bfloat162_rn(make_float2(acc[j].x * id, acc[j].y * id));
        ow[j] = *(unsigned*)&b;
    }
    ((uint4*)g_aggb)[(size_t)node * TPN + f] = o;
}

// ---- bf16 dual GEMM + fused BN-stats: g_hpre = g_aggb@W1 + A2@W2  (bias absorbed by BN) ----
// BM=128, BN=128, BK=16; 256 threads = 8 warps (2M x 4N), warp tile 64x32, mma m16n8k16.
template <int K, bool A2X>
__global__ void __launch_bounds__(256, 2)
k_gemm_bf16(const float* __restrict__ W1, const float* __restrict__ W2, int layer) {
    __shared__ __nv_bfloat16 As[128 * 24];   // [row][k], stride 24 bf16 (48B)
    __shared__ __nv_bfloat16 Bs[128 * 24];   // [n][k],  stride 24 bf16

    int tid = threadIdx.x;
    int lane = tid & 31;
    int wid = tid >> 5;
    int warp_m = wid & 1;              // 64 rows each
    int warp_n = wid >> 1;             // 32 cols each
    int g = lane >> 2;                 // 0..7
    int tg = lane & 3;                 // 0..3
    int blockRow = blockIdx.x * 128;

    float acc[4][4][4];
#pragma unroll
    for (int mt = 0; mt < 4; mt++)
#pragma unroll
        for (int nt = 0; nt < 4; nt++)
#pragma unroll
            for (int q = 0; q < 4; q++) acc[mt][nt][q] = 0.0f;

    const __nv_bfloat16* Aseg = g_aggb;
    const float* Wseg = W1;
#pragma unroll 1
    for (int seg = 0; seg < 2; seg++) {
#pragma unroll 1
        for (int k0 = 0; k0 < K; k0 += 16) {
            // A tile: 128 rows x 16 k bf16 (uint4 = 8 bf16 per thread, 2 threads/row)
            {
                int r = tid >> 1;
                int half = tid & 1;
                int gr = blockRow + r;
                uint4 v = make_uint4(0u, 0u, 0u, 0u);
                if (gr < NN) v = *(const uint4*)(Aseg + (size_t)gr * K + k0 + half * 8);
                *(uint4*)&As[r * 24 + half * 8] = v;
            }
            // B tile: W[k0+kk][n] fp32 -> Bs[n][kk] bf16 (transposed store)
            {
                int kk = tid >> 4;                 // 0..15
                int n0 = (tid & 15) * 8;           // 8 n per thread
                float4 w0 = *(const float4*)(Wseg + (size_t)(k0 + kk) * 128 + n0);
                float4 w1 = *(const float4*)(Wseg + (size_t)(k0 + kk) * 128 + n0 + 4);
                Bs[(n0 + 0) * 24 + kk] = __float2bfloat16_rn(w0.x);
                Bs[(n0 + 1) * 24 + kk] = __float2bfloat16_rn(w0.y);
                Bs[(n0 + 2) * 24 + kk] = __float2bfloat16_rn(w0.z);
                Bs[(n0 + 3) * 24 + kk] = __float2bfloat16_rn(w0.w);
                Bs[(n0 + 4) * 24 + kk] = __float2bfloat16_rn(w1.x);
                Bs[(n0 + 5) * 24 + kk] = __float2bfloat16_rn(w1.y);
                Bs[(n0 + 6) * 24 + kk] = __float2bfloat16_rn(w1.z);
                Bs[(n0 + 7) * 24 + kk] = __float2bfloat16_rn(w1.w);
            }
            __syncthreads();
            {
                unsigned a[4][4], b[4][2];
#pragma unroll
                for (int mt = 0; mt < 4; mt++) {
                    int r = warp_m * 64 + mt * 16 + g;
                    a[mt][0] = *(const unsigned*)&As[r * 24 + 2 * tg];
                    a[mt][1] = *(const unsigned*)&As[(r + 8) * 24 + 2 * tg];
                    a[mt][2] = *(const unsigned*)&As[r * 24 + 2 * tg + 8];
                    a[mt][3] = *(const unsigned*)&As[(r + 8) * 24 + 2 * tg + 8];
                }
#pragma unroll
                for (int nt = 0; nt < 4; nt++) {
                    int c = warp_n * 32 + nt * 8 + g;
                    b[nt][0] = *(const unsigned*)&Bs[c * 24 + 2 * tg];
                    b[nt][1] = *(const unsigned*)&Bs[c * 24 + 2 * tg + 8];
                }
#pragma unroll
                for (int mt = 0; mt < 4; mt++)
#pragma unroll
                    for (int nt = 0; nt < 4; nt++)
                        mma_bf16(acc[mt][nt], a[mt], b[nt]);
            }
            __syncthreads();
        }
        Aseg = A2X ? g_xb : g_hb;
        Wseg = W2;
    }

    // ---- epilogue: store acc -> g_hpre, fused per-column sum/sumsq -> atomics ----
#pragma unroll
    for (int mt = 0; mt < 4; mt++) {
        int r0 = blockRow + warp_m * 64 + mt * 16 + g;
#pragma unroll
        for (int nt = 0; nt < 4; nt++) {
            int c = warp_n * 32 + nt * 8 + 2 * tg;
            if (r0 < NN)
                *(float2*)(g_hpre + (size_t)r0 * 128 + c) =
                    make_float2(acc[mt][nt][0], acc[mt][nt][1]);
            if (r0 + 8 < NN)
                *(float2*)(g_hpre + (size_t)(r0 + 8) * 128 + c) =
                    make_float2(acc[mt][nt][2], acc[mt][nt][3]);
        }
    }
#pragma unroll
    for (int nt = 0; nt < 4; nt++) {
        float s0 = 0.f, s1 = 0.f, q0 = 0.f, q1 = 0.f;
#pragma unroll
        for (int mt = 0; mt < 4; mt++) {
            float a0 = acc[mt][nt][0], a1 = acc[mt][nt][1];
            float a2 = acc[mt][nt][2], a3 = acc[mt][nt][3];
            s0 += a0 + a2; s1 += a1 + a3;
            q0 += a0 * a0 + a2 * a2; q1 += a1 * a1 + a3 * a3;
        }
#pragma unroll
        for (int off = 4; off < 32; off <<= 1) {
            s0 += __shfl_xor_sync(0xffffffffu, s0, off);
            s1 += __shfl_xor_sync(0xffffffffu, s1, off);
            q0 += __shfl_xor_sync(0xffffffffu, q0, off);
            q1 += __shfl_xor_sync(0xffffffffu, q1, off);
        }
        if (lane < 4) {                       // g == 0
            int c = warp_n * 32 + nt * 8 + 2 * tg;
            atomicAdd(&g_colsum[layer][c], s0);
            atomicAdd(&g_colsum[layer][c + 1], s1);
            atomicAdd(&g_colsumsq[layer][c], q0);
            atomicAdd(&g_colsumsq[layer][c + 1], q1);
        }
    }
}

// ---- BN apply + ReLU: g_hb = bf16(relu(bn(g_hpre))); optional fused pooling ----
__global__ void k_bn_apply(const float* __restrict__ gamma, const float* __restrict__ beta,
                           const int* __restrict__ batch, int layer, int do_pool, int write_h) {
    int i = blockIdx.x * blockDim.x + threadIdx.x;   // NN*32 groups of 4 cols
    if (i >= NN * 32) return;
    int row = i >> 5;
    int c0 = (i & 31) * 4;
    const float invN = 1.0f / (float)NN;
    float4 hv = ((const float4*)g_hpre)[i];
    float o[4] = {hv.x, hv.y, hv.z, hv.w};
#pragma unroll
    for (int j = 0; j < 4; j++) {
        int col = c0 + j;
        float mu = g_colsum[layer][col] * invN;
        float var = g_colsumsq[layer][col] * invN - mu * mu;
        float v = (o[j] - mu) * rsqrtf(var + BN_EPS) * gamma[col] + beta[col];
        o[j] = fmaxf(v, 0.0f);
    }
    if (write_h) {
        __nv_bfloat162 lo = __float22bfloat162_rn(make_float2(o[0], o[1]));
        __nv_bfloat162 hi = __float22bfloat162_rn(make_float2(o[2], o[3]));
        uint2 ov;
        ov.x = *(unsigned*)&lo;
        ov.y = *(unsigned*)&hi;
        ((uint2*)g_hb)[i] = ov;
    }
    if (do_pool) {
        int b = clampi(batch[row], NG - 1);
        float* p = &g_pooled[b * 128 + c0];
        atomicAdd(p + 0, o[0]);
        atomicAdd(p + 1, o[1]);
        atomicAdd(p + 2, o[2]);
        atomicAdd(p + 3, o[3]);
    }
}

// ---------------- final MLP + sigmoid ----------------
__global__ void k_mlp(const float* __restrict__ fc1W, const float* __restrict__ fc1b,
                      const float* __restrict__ fc2W, const float* __restrict__ fc2b,
                      float* __restrict__ out) {
    int g = blockIdx.x;          // 256 blocks
    int t = threadIdx.x;         // 64 threads
    __shared__ float p[128];
    __shared__ float zred[2];
    float cnt = fmaxf(g_gcount[g], 1.0f);
    p[t]      = g_pooled[g * 128 + t] / cnt;
    p[t + 64] = g_pooled[g * 128 + 64 + t] / cnt;
    __syncthreads();
    float z = fc1b[t];
#pragma unroll 8
    for (int k = 0; k < 128; k++) z += p[k] * fc1W[k * 64 + t];
    z = fmaxf(z, 0.0f) * fc2W[t];
#pragma unroll
    for (int off = 16; off; off >>= 1) z += __shfl_down_sync(0xffffffffu, z, off);
    if ((t & 31) == 0) zred[t >> 5] = z;
    __syncthreads();
    if (t == 0) {
        float s = zred[0] + zred[1] + fc2b[0];
        out[g] = 1.0f / (1.0f + expf(-s));
    }
}

// ---------------- host launcher: kernel launches ONLY ----------------
extern "C" void kernel_launch(void* const* d_in, const int* in_sizes, int n_in,
                              void* d_out, int out_size) {
    const float* x     = (const float*)d_in[0];
    const int*   ei    = (const int*)d_in[1];     // int64 narrowed to int32 by harness
    const int*   batch = (const int*)d_in[2];
    const float* Wn0 = (const float*)d_in[3];
    const float* Wr0 = (const float*)d_in[4];
    const float* Wn1 = (const float*)d_in[6];
    const float* Wr1 = (const float*)d_in[7];
    const float* Wn2 = (const float*)d_in[9];
    const float* Wr2 = (const float*)d_in[10];
    const float* gamma = (const float*)d_in[12]; // [3,128]
    const float* beta  = (const float*)d_in[13];
    const float* fc1W = (const float*)d_in[14];
    const float* fc1b = (const float*)d_in[15];
    const float* fc2W = (const float*)d_in[16];
    const float* fc2b = (const float*)d_in[17];
    float* out = (float*)d_out;

    // ---- graph structure + input conversion ----
    k_zero_main<<<(NN + 255) / 256, 256>>>();
    k_deg_batch<<<(NE + 255) / 256, 256>>>(ei, batch);
    k_scan<<<1, 1024>>>();
    k_fill<<<(NE + 255) / 256, 256>>>(ei);
    k_cvt_x<<<(NN * 16 + 255) / 256, 256>>>(x);

    const int gemmGrid = (NN + 127) / 128;
    const int bnApplyGrid = (NN * 32 + 255) / 256;

    // ---- layer 0: in_dim 64 ----
    k_aggregate<64, true><<<(NN + 31) / 32, 256>>>();
    k_gemm_bf16<64, true><<<gemmGrid, 256>>>(Wn0, Wr0, 0);
    k_bn_apply<<<bnApplyGrid, 256>>>(gamma + 0 * HID, beta + 0 * HID, batch, 0, 0, 1);

    // ---- layer 1 ----
    k_aggregate<128, false><<<(NN + 15) / 16, 256>>>();
    k_gemm_bf16<128, false><<<gemmGrid, 256>>>(Wn1, Wr1, 1);
    k_bn_apply<<<bnApplyGrid, 256>>>(gamma + 1 * HID, beta + 1 * HID, batch, 1, 0, 1);

    // ---- layer 2 (pooling fused; no h write needed) ----
    k_aggregate<128, false><<<(NN + 15) / 16, 256>>>();
    k_gemm_bf16<128, false><<<gemmGrid, 256>>>(Wn2, Wr2, 2);
    k_bn_apply<<<bnApplyGrid, 256>>>(gamma + 2 * HID, beta + 2 * HID, batch, 2, 1, 0);

    // ---- MLP head ----
    k_mlp<<<NG, 64>>>(fc1W, fc1b, fc2W, fc2b, out);
}